// round 16
// baseline (speedup 1.0000x reference)
#include <cuda_runtime.h>
#include <cuda_fp16.h>
#include <cstdint>

#define BB 8
#define TT 2048
#define CC 1024
#define HH 64
#define NQT 32
#define SPL 2
#define QSCALE 0.1803368801111601f   // 0.125 * log2(e)

__device__ __align__(16) __half g_qh[BB*TT*HH];
__device__ __align__(16) __half g_kh[BB*TT*HH];
__device__ __align__(16) __half g_vh[BB*TT*HH];
// fused fp16 W rows k, 192 cols (pad 200).
// Layout: K[0:32] | Q[0:32] | V[0:32] | K[32:64] | Q[32:64] | V[32:64]
__device__ __align__(16) __half g_wf[CC*200];
__device__ __align__(16) __half g_pOh[BB*NQT*SPL*64*64];   // fp16 partials
__device__ float2 g_pML[BB*NQT*SPL*64];                    // (m, l) in log2 domain

__device__ __forceinline__ float ex2(float x) {
    float y;
    asm("ex2.approx.f32 %0, %1;" : "=f"(y) : "f"(x));
    return y;
}
__device__ __forceinline__ uint32_t smaddr(const void* p) {
    return (uint32_t)__cvta_generic_to_shared(p);
}
__device__ __forceinline__ void ldsm4(uint32_t r[4], uint32_t a) {
    asm volatile("ldmatrix.sync.aligned.m8n8.x4.shared.b16 {%0,%1,%2,%3}, [%4];\n"
        : "=r"(r[0]), "=r"(r[1]), "=r"(r[2]), "=r"(r[3]) : "r"(a));
}
__device__ __forceinline__ void ldsm4t(uint32_t r[4], uint32_t a) {
    asm volatile("ldmatrix.sync.aligned.m8n8.x4.trans.shared.b16 {%0,%1,%2,%3}, [%4];\n"
        : "=r"(r[0]), "=r"(r[1]), "=r"(r[2]), "=r"(r[3]) : "r"(a));
}
__device__ __forceinline__ void mma16816(float d[4], const uint32_t a[4], const uint32_t b[2]) {
    asm volatile("mma.sync.aligned.m16n8k16.row.col.f32.f16.f16.f32 "
        "{%0,%1,%2,%3}, {%4,%5,%6,%7}, {%8,%9}, {%0,%1,%2,%3};\n"
        : "+f"(d[0]), "+f"(d[1]), "+f"(d[2]), "+f"(d[3])
        : "r"(a[0]), "r"(a[1]), "r"(a[2]), "r"(a[3]), "r"(b[0]), "r"(b[1]));
}
__device__ __forceinline__ uint32_t packh2(float a, float b) {
    __half2 h = __floats2half2_rn(a, b);
    return *reinterpret_cast<uint32_t*>(&h);
}
#define CPA16(dst, src) \
    asm volatile("cp.async.cg.shared.global [%0], [%1], 16;" :: "r"(dst), "l"(src))
#define CPA_COMMIT() asm volatile("cp.async.commit_group;")

// ---------------------------------------------------------------------------
// W prep: layout K[0:32]|Q[0:32]|V[0:32]|K[32:64]|Q[32:64]|V[32:64]
// ---------------------------------------------------------------------------
__global__ void wprep_kernel(const float* __restrict__ Wk,
                             const float* __restrict__ Wq,
                             const float* __restrict__ Wv)
{
    int idx = blockIdx.x*256 + threadIdx.x;       // over 1024*192
    int k = idx / 192, n = idx % 192;
    int wgp = n / 96, r = n % 96;
    int type = r >> 5;                            // 0=K 1=Q 2=V
    int h = wgp*32 + (r & 31);
    const float* W = (type == 0) ? Wk : (type == 1) ? Wq : Wv;
    g_wf[(size_t)k*200 + n] = __float2half_rn(W[(size_t)k*HH + h]);
}

// ---------------------------------------------------------------------------
// Projection: 64 rows/CTA, 256 thr, K chunk 64, pure fp16.
// Dynamic smem 69632 B: xh 2x9216 @0, ws 2x25600 @18432.
// row_base allows split launches for stream overlap.
// ---------------------------------------------------------------------------
#define PROJ_SMEM 69632

__device__ __forceinline__ void w_stage64(char* wsb, int k0, int tid) {
    #pragma unroll
    for (int i = 0; i < 6; i++) {
        int j = tid + i*256;                      // 64 rows x 24 groups
        int r = j / 24, c8 = (j % 24)*8;
        CPA16(smaddr(wsb + r*400 + c8*2), &g_wf[(size_t)(k0 + r)*200 + c8]);
    }
}

__global__ __launch_bounds__(256, 2) void proj_kernel(const float* __restrict__ x,
                                                      int row_base)
{
    extern __shared__ char sm[];
    const int tid = threadIdx.x;
    const int wid = tid >> 5, lane = tid & 31;
    const int wg = wid >> 2, w4 = wid & 3;
    const int row0 = row_base + blockIdx.x * 64;
    const int g = lane >> 3, rl = lane & 7;
    const int xr = tid >> 4;                      // 0..15
    const int xc = (tid & 15)*4;                  // 0..60

    float acc[12][4];
    #pragma unroll
    for (int j = 0; j < 12; j++)
        #pragma unroll
        for (int e = 0; e < 4; e++) acc[j][e] = 0.f;

    w_stage64(sm + 18432, 0, tid);
    CPA_COMMIT();
    float4 px[4];
    #pragma unroll
    for (int i = 0; i < 4; i++)
        px[i] = *(const float4*)&x[(size_t)(row0 + i*16 + xr)*CC + xc];

    #pragma unroll 1
    for (int c = 0; c < 16; c++) {
        const int buf = c & 1;
        char* xh  = sm + buf*9216;
        char* wsb = sm + 18432 + buf*25600;
        __syncthreads();                          // prev-chunk readers done
        #pragma unroll
        for (int i = 0; i < 4; i++) {             // STS chunk c (fp16)
            int row = i*16 + xr;
            float4 v = px[i];
            *(uint2*)(xh + row*144 + xc*2) = make_uint2(
                packh2(v.x, v.y), packh2(v.z, v.w));
        }
        if (c + 1 < 16) {
            w_stage64(sm + 18432 + (buf ^ 1)*25600, (c+1)*64, tid);
            CPA_COMMIT();
            #pragma unroll
            for (int i = 0; i < 4; i++)
                px[i] = *(const float4*)
                    &x[(size_t)(row0 + i*16 + xr)*CC + (c+1)*64 + xc];
            asm volatile("cp.async.wait_group 1;");
        } else {
            asm volatile("cp.async.wait_group 0;");
        }
        __syncthreads();                          // chunk c staged

        #pragma unroll
        for (int sub = 0; sub < 4; sub++) {
            uint32_t ah[4];
            int ar = w4*16 + (lane & 15), ac = sub*16 + ((lane >> 4) << 3);
            ldsm4(ah, smaddr(xh + ar*144 + ac*2));
            int br = sub*16 + (g & 1)*8 + rl;
            #pragma unroll
            for (int j = 0; j < 6; j++) {
                int bc = wg*96 + j*16 + (g >> 1)*8;
                uint32_t bh[4];
                ldsm4t(bh, smaddr(wsb + br*400 + bc*2));
                mma16816(acc[2*j],   ah, bh);
                mma16816(acc[2*j+1], ah, bh + 2);
            }
        }
    }

    // epilogue (layout per wg: K[32] | Q[32] | V[32], h = wg*32 + (r&31))
    const int rl4 = lane >> 2, q2 = (lane & 3)*2;
    #pragma unroll
    for (int j = 0; j < 6; j++) {
        #pragma unroll
        for (int h2 = 0; h2 < 2; h2++) {
            int r = j*16 + h2*8 + q2;              // 0..95 within wg
            int type = r >> 5;
            int hc = wg*32 + (r & 31);
            #pragma unroll
            for (int er = 0; er < 2; er++) {
                float v0 = acc[2*j+h2][er*2], v1 = acc[2*j+h2][er*2+1];
                size_t roff = (size_t)(row0 + w4*16 + rl4 + er*8)*HH + hc;
                if (type == 0) {
                    *(__half2*)&g_kh[roff] = __floats2half2_rn(v0, v1);
                } else if (type == 2) {
                    *(__half2*)&g_vh[roff] = __floats2half2_rn(v0, v1);
                } else {
                    *(__half2*)&g_qh[roff] =
                        __floats2half2_rn(v0*QSCALE, v1*QSCALE);
                }
            }
        }
    }
}

// ---------------------------------------------------------------------------
// Flash attention, split-KV (SPL=2): CTA (qt, js) does kt = js, js+2, ... <= qt.
// q pre-scaled by 0.125*log2(e); softmax in exp2 domain. Partials fp16.
// smem: Qh [64][72] @0 (9216 B), KV bufs @4608 halfs.
// ---------------------------------------------------------------------------
#define ATT_SMEM_BYTES ((4608 + 2*9216) * 2)      // 46080

__device__ __forceinline__ void kv_prefetch(__half* sh, int buf, size_t gbase,
                                            int tid)
{
    __half* base = sh + 4608 + buf*9216;
    #pragma unroll
    for (int i = 0; i < 8; i++) {
        int j = tid + i*128;
        int surf = j >> 9, rc = j & 511;
        int r = rc >> 3, c = (rc & 7)*8;
        CPA16(smaddr(base + surf*4608 + r*72 + c),
              (surf ? g_vh : g_kh) + gbase + r*64 + c);
    }
}

__global__ __launch_bounds__(128) void attn_kernel(int b0)
{
    extern __shared__ __half sh[];
    __half* Qh = sh;

    const int tid = threadIdx.x;
    const int w = tid >> 5, lane = tid & 31;
    const int qt = NQT - 1 - ((int)blockIdx.x >> 1);
    const int js = blockIdx.x & 1;
    const int b = blockIdx.y + b0;
    const int chunk = (b*NQT + qt)*SPL + js;
    __half* poh = g_pOh + (size_t)chunk*4096;

    if (js > qt) return;                          // merge handles empty splits

    const size_t kvb = (size_t)b*TT*HH;
    kv_prefetch(sh, 0, kvb + (size_t)js*64*HH, tid);
    CPA_COMMIT();

    {
        const size_t qb = kvb + (size_t)qt*64*HH;
        #pragma unroll
        for (int i = 0; i < 4; i++) {
            int idx = tid + i*128; int r = idx >> 3, c = (idx & 7)*8;
            *(int4*)&Qh[r*72 + c] = *(const int4*)&g_qh[qb + r*64 + c];
        }
    }
    __syncthreads();

    uint32_t aq[4][4];
    #pragma unroll
    for (int kc = 0; kc < 4; kc++) {
        int r = w*16 + (lane & 15), c = kc*16 + ((lane >> 4) << 3);
        ldsm4(aq[kc], smaddr(&Qh[r*72 + c]));
    }

    float o[8][4];
    #pragma unroll
    for (int nt = 0; nt < 8; nt++)
        #pragma unroll
        for (int e = 0; e < 4; e++) o[nt][e] = 0.f;
    float m0 = -1e9f, m1 = -1e9f, l0 = 0.f, l1 = 0.f;

    #pragma unroll 1
    for (int kt = js; kt <= qt; kt += SPL) {
        const int step = (kt - js) >> 1;
        __syncthreads();
        if (kt + SPL <= qt) {
            kv_prefetch(sh, (step & 1) ^ 1,
                        kvb + (size_t)(kt + SPL)*64*HH, tid);
            CPA_COMMIT();
            asm volatile("cp.async.wait_group 1;");
        } else {
            asm volatile("cp.async.wait_group 0;");
        }
        __syncthreads();

        __half* Khp = sh + 4608 + (step & 1)*9216;
        __half* Vsp = Khp + 4608;

        float s[8][4];
        #pragma unroll
        for (int nt = 0; nt < 8; nt++)
            #pragma unroll
            for (int e = 0; e < 4; e++) s[nt][e] = 0.f;
        const int g = lane >> 3, rl8 = lane & 7;
        #pragma unroll
        for (int kc = 0; kc < 4; kc++) {
            #pragma unroll
            for (int jj = 0; jj < 4; jj++) {
                int r = jj*16 + (g >> 1)*8 + rl8;
                int ccol = kc*16 + (g & 1)*8;
                uint32_t bh[4];
                ldsm4(bh, smaddr(&Khp[r*72 + ccol]));
                mma16816(s[2*jj],   aq[kc], bh);
                mma16816(s[2*jj+1], aq[kc], bh + 2);
            }
        }

        if (kt == qt) {
            int r0l = w*16 + (lane >> 2);
            int c0l = (lane & 3)*2;
            #pragma unroll
            for (int nt = 0; nt < 8; nt++) {
                int c = nt*8 + c0l;
                if (c     > r0l)     s[nt][0] = -1e9f;
                if (c + 1 > r0l)     s[nt][1] = -1e9f;
                if (c     > r0l + 8) s[nt][2] = -1e9f;
                if (c + 1 > r0l + 8) s[nt][3] = -1e9f;
            }
        }

        float rm0 = -1e9f, rm1 = -1e9f;
        #pragma unroll
        for (int nt = 0; nt < 8; nt++) {
            rm0 = fmaxf(rm0, fmaxf(s[nt][0], s[nt][1]));
            rm1 = fmaxf(rm1, fmaxf(s[nt][2], s[nt][3]));
        }
        rm0 = fmaxf(rm0, __shfl_xor_sync(0xffffffffu, rm0, 1));
        rm0 = fmaxf(rm0, __shfl_xor_sync(0xffffffffu, rm0, 2));
        rm1 = fmaxf(rm1, __shfl_xor_sync(0xffffffffu, rm1, 1));
        rm1 = fmaxf(rm1, __shfl_xor_sync(0xffffffffu, rm1, 2));
        float mn0 = fmaxf(m0, rm0), mn1 = fmaxf(m1, rm1);
        float corr0 = ex2(m0 - mn0), corr1 = ex2(m1 - mn1);
        m0 = mn0; m1 = mn1;
        float rs0 = 0.f, rs1 = 0.f;
        #pragma unroll
        for (int nt = 0; nt < 8; nt++) {
            s[nt][0] = ex2(s[nt][0] - mn0); rs0 += s[nt][0];
            s[nt][1] = ex2(s[nt][1] - mn0); rs0 += s[nt][1];
            s[nt][2] = ex2(s[nt][2] - mn1); rs1 += s[nt][2];
            s[nt][3] = ex2(s[nt][3] - mn1); rs1 += s[nt][3];
        }
        rs0 += __shfl_xor_sync(0xffffffffu, rs0, 1);
        rs0 += __shfl_xor_sync(0xffffffffu, rs0, 2);
        rs1 += __shfl_xor_sync(0xffffffffu, rs1, 1);
        rs1 += __shfl_xor_sync(0xffffffffu, rs1, 2);
        l0 = l0*corr0 + rs0;
        l1 = l1*corr1 + rs1;
        #pragma unroll
        for (int nt = 0; nt < 8; nt++) {
            o[nt][0] *= corr0; o[nt][1] *= corr0;
            o[nt][2] *= corr1; o[nt][3] *= corr1;
        }

        #pragma unroll
        for (int kc = 0; kc < 4; kc++) {
            uint32_t ap[4];
            ap[0] = packh2(s[2*kc][0],   s[2*kc][1]);
            ap[1] = packh2(s[2*kc][2],   s[2*kc][3]);
            ap[2] = packh2(s[2*kc+1][0], s[2*kc+1][1]);
            ap[3] = packh2(s[2*kc+1][2], s[2*kc+1][3]);
            #pragma unroll
            for (int jj = 0; jj < 4; jj++) {
                int r = kc*16 + (g & 1)*8 + rl8;
                int ccol = jj*16 + (g >> 1)*8;
                uint32_t vb[4];
                ldsm4t(vb, smaddr(&Vsp[r*72 + ccol]));
                mma16816(o[2*jj],   ap, vb);
                mma16816(o[2*jj+1], ap, vb + 2);
            }
        }
    }

    const int r0 = w*16 + (lane >> 2);
    #pragma unroll
    for (int nt = 0; nt < 8; nt++) {
        int c = nt*8 + (lane & 3)*2;
        *(uint32_t*)&poh[r0*64 + c]     = packh2(o[nt][0], o[nt][1]);
        *(uint32_t*)&poh[(r0+8)*64 + c] = packh2(o[nt][2], o[nt][3]);
    }
    if ((lane & 3) == 0) {
        g_pML[chunk*64 + r0]     = make_float2(m0, l0);
        g_pML[chunk*64 + r0 + 8] = make_float2(m1, l1);
    }
}

// ---------------------------------------------------------------------------
// Merge (SPL=2): fp16 partials, exp2 domain; split 1 empty when qt == 0.
// 512 threads; thread = (row, 8-col group).
// ---------------------------------------------------------------------------
__global__ __launch_bounds__(512) void merge_kernel(float* __restrict__ out, int b0)
{
    const int qt = blockIdx.x, b = blockIdx.y + b0;
    const int tid = threadIdx.x;
    const int r = tid >> 3;                       // 0..63
    const int c8 = (tid & 7)*8;
    const int c0 = (b*NQT + qt)*SPL;

    float2 ml[SPL];
    uint4 ph[SPL];
    #pragma unroll
    for (int j = 0; j < SPL; j++) {
        if (j <= qt) {
            ml[j] = g_pML[(c0 + j)*64 + r];
            ph[j] = *(const uint4*)&g_pOh[(size_t)(c0 + j)*4096 + r*64 + c8];
        } else {
            ml[j] = make_float2(-1e30f, 0.f);
            ph[j] = make_uint4(0u, 0u, 0u, 0u);
        }
    }
    float M = fmaxf(ml[0].x, ml[1].x);
    float wsum = 0.f, wj[SPL];
    #pragma unroll
    for (int j = 0; j < SPL; j++) {
        wj[j] = ex2(ml[j].x - M);
        wsum += wj[j]*ml[j].y;
    }
    const float inv = 1.0f/wsum;

    float a[8];
    #pragma unroll
    for (int i = 0; i < 8; i++) a[i] = 0.f;
    #pragma unroll
    for (int j = 0; j < SPL; j++) {
        const uint32_t* u = (const uint32_t*)&ph[j];
        #pragma unroll
        for (int p = 0; p < 4; p++) {
            float2 v = __half22float2(*(const __half2*)&u[p]);
            a[2*p]   += wj[j]*v.x;
            a[2*p+1] += wj[j]*v.y;
        }
    }
    size_t off = ((size_t)b*TT + qt*64 + r)*HH + c8;
    *(float4*)&out[off]     = make_float4(a[0]*inv, a[1]*inv, a[2]*inv, a[3]*inv);
    *(float4*)&out[off + 4] = make_float4(a[4]*inv, a[5]*inv, a[6]*inv, a[7]*inv);
}

extern "C" void kernel_launch(void* const* d_in, const int* in_sizes, int n_in,
                              void* d_out, int out_size) {
    const float* x  = (const float*)d_in[0];
    const float* Wk = (const float*)d_in[1];
    const float* Wq = (const float*)d_in[2];
    const float* Wv = (const float*)d_in[3];
    float* out = (float*)d_out;

    static int init = 0;
    static cudaStream_t s1;
    static cudaEvent_t eA, e1;
    if (!init) {
        cudaFuncSetAttribute(proj_kernel,
            cudaFuncAttributeMaxDynamicSharedMemorySize, PROJ_SMEM);
        cudaFuncSetAttribute(attn_kernel,
            cudaFuncAttributeMaxDynamicSharedMemorySize, ATT_SMEM_BYTES);
        cudaStreamCreateWithFlags(&s1, cudaStreamNonBlocking);
        cudaEventCreateWithFlags(&eA, cudaEventDisableTiming);
        cudaEventCreateWithFlags(&e1, cudaEventDisableTiming);
        init = 1;
    }

    wprep_kernel<<<768, 256>>>(Wk, Wq, Wv);
    proj_kernel<<<128, 256, PROJ_SMEM>>>(x, 0);        // batches 0-3
    cudaEventRecord(eA, 0);
    proj_kernel<<<128, 256, PROJ_SMEM>>>(x, 4*TT);     // batches 4-7

    cudaStreamWaitEvent(s1, eA, 0);                    // attn 0-3 ∥ proj 4-7
    attn_kernel<<<dim3(NQT*SPL, 4), 128, ATT_SMEM_BYTES, s1>>>(0);
    merge_kernel<<<dim3(NQT, 4), 512, 0, s1>>>(out, 0);
    cudaEventRecord(e1, s1);

    attn_kernel<<<dim3(NQT*SPL, 4), 128, ATT_SMEM_BYTES>>>(4);
    merge_kernel<<<dim3(NQT, 4), 512>>>(out, 4);
    cudaStreamWaitEvent(0, e1, 0);                     // join
}

// round 17
// speedup vs baseline: 1.2061x; 1.2061x over previous
#include <cuda_runtime.h>
#include <cuda_fp16.h>
#include <cstdint>

#define BB 8
#define TT 2048
#define CC 1024
#define HH 64
#define NQT 32
#define SPL 4
#define QSCALE 0.1803368801111601f   // 0.125 * log2(e)

__device__ __align__(16) __half g_qh[BB*TT*HH];
__device__ __align__(16) __half g_kh[BB*TT*HH];
__device__ __align__(16) __half g_vh[BB*TT*HH];
// fused fp16 W rows k, 192 cols (pad 200).
// Layout: K[0:32] | Q[0:32] | V[0:32] | K[32:64] | Q[32:64] | V[32:64]
__device__ __align__(16) __half g_wf[CC*200];
__device__ __align__(16) __half g_pOh[BB*NQT*SPL*64*64];   // fp16 partials
__device__ float2 g_pML[BB*NQT*SPL*64];                    // (m, l) in log2 domain

__device__ __forceinline__ float ex2(float x) {
    float y;
    asm("ex2.approx.f32 %0, %1;" : "=f"(y) : "f"(x));
    return y;
}
__device__ __forceinline__ uint32_t smaddr(const void* p) {
    return (uint32_t)__cvta_generic_to_shared(p);
}
__device__ __forceinline__ void ldsm4(uint32_t r[4], uint32_t a) {
    asm volatile("ldmatrix.sync.aligned.m8n8.x4.shared.b16 {%0,%1,%2,%3}, [%4];\n"
        : "=r"(r[0]), "=r"(r[1]), "=r"(r[2]), "=r"(r[3]) : "r"(a));
}
__device__ __forceinline__ void ldsm4t(uint32_t r[4], uint32_t a) {
    asm volatile("ldmatrix.sync.aligned.m8n8.x4.trans.shared.b16 {%0,%1,%2,%3}, [%4];\n"
        : "=r"(r[0]), "=r"(r[1]), "=r"(r[2]), "=r"(r[3]) : "r"(a));
}
__device__ __forceinline__ void mma16816(float d[4], const uint32_t a[4], const uint32_t b[2]) {
    asm volatile("mma.sync.aligned.m16n8k16.row.col.f32.f16.f16.f32 "
        "{%0,%1,%2,%3}, {%4,%5,%6,%7}, {%8,%9}, {%0,%1,%2,%3};\n"
        : "+f"(d[0]), "+f"(d[1]), "+f"(d[2]), "+f"(d[3])
        : "r"(a[0]), "r"(a[1]), "r"(a[2]), "r"(a[3]), "r"(b[0]), "r"(b[1]));
}
__device__ __forceinline__ uint32_t packh2(float a, float b) {
    __half2 h = __floats2half2_rn(a, b);
    return *reinterpret_cast<uint32_t*>(&h);
}
#define CPA16(dst, src) \
    asm volatile("cp.async.cg.shared.global [%0], [%1], 16;" :: "r"(dst), "l"(src))
#define CPA_COMMIT() asm volatile("cp.async.commit_group;")

// ---------------------------------------------------------------------------
// W prep: layout K[0:32]|Q[0:32]|V[0:32]|K[32:64]|Q[32:64]|V[32:64]
// ---------------------------------------------------------------------------
__global__ void wprep_kernel(const float* __restrict__ Wk,
                             const float* __restrict__ Wq,
                             const float* __restrict__ Wv)
{
    int idx = blockIdx.x*256 + threadIdx.x;       // over 1024*192
    int k = idx / 192, n = idx % 192;
    int wgp = n / 96, r = n % 96;
    int type = r >> 5;                            // 0=K 1=Q 2=V
    int h = wgp*32 + (r & 31);
    const float* W = (type == 0) ? Wk : (type == 1) ? Wq : Wv;
    g_wf[(size_t)k*200 + n] = __float2half_rn(W[(size_t)k*HH + h]);
}

// ---------------------------------------------------------------------------
// Projection: [16384 x 1024] x [1024 x 192]. 256 CTAs x 64 rows, 256 thr.
// K chunk = 64. Pure fp16 path.
// Dynamic smem 69632 B: xh 2x9216 @0, ws 2x25600 @18432.
// ---------------------------------------------------------------------------
#define PROJ_SMEM 69632

__device__ __forceinline__ void w_stage64(char* wsb, int k0, int tid) {
    #pragma unroll
    for (int i = 0; i < 6; i++) {
        int j = tid + i*256;                      // 64 rows x 24 groups
        int r = j / 24, c8 = (j % 24)*8;
        CPA16(smaddr(wsb + r*400 + c8*2), &g_wf[(size_t)(k0 + r)*200 + c8]);
    }
}

__global__ __launch_bounds__(256, 2) void proj_kernel(const float* __restrict__ x)
{
    extern __shared__ char sm[];
    const int tid = threadIdx.x;
    const int wid = tid >> 5, lane = tid & 31;
    const int wg = wid >> 2, w4 = wid & 3;
    const int row0 = blockIdx.x * 64;
    const int g = lane >> 3, rl = lane & 7;
    const int xr = tid >> 4;                      // 0..15
    const int xc = (tid & 15)*4;                  // 0..60

    float acc[12][4];
    #pragma unroll
    for (int j = 0; j < 12; j++)
        #pragma unroll
        for (int e = 0; e < 4; e++) acc[j][e] = 0.f;

    w_stage64(sm + 18432, 0, tid);
    CPA_COMMIT();
    float4 px[4];
    #pragma unroll
    for (int i = 0; i < 4; i++)
        px[i] = *(const float4*)&x[(size_t)(row0 + i*16 + xr)*CC + xc];

    #pragma unroll 1
    for (int c = 0; c < 16; c++) {
        const int buf = c & 1;
        char* xh  = sm + buf*9216;
        char* wsb = sm + 18432 + buf*25600;
        __syncthreads();                          // prev-chunk readers done
        #pragma unroll
        for (int i = 0; i < 4; i++) {             // STS chunk c (fp16)
            int row = i*16 + xr;
            float4 v = px[i];
            *(uint2*)(xh + row*144 + xc*2) = make_uint2(
                packh2(v.x, v.y), packh2(v.z, v.w));
        }
        if (c + 1 < 16) {
            w_stage64(sm + 18432 + (buf ^ 1)*25600, (c+1)*64, tid);
            CPA_COMMIT();
            #pragma unroll
            for (int i = 0; i < 4; i++)
                px[i] = *(const float4*)
                    &x[(size_t)(row0 + i*16 + xr)*CC + (c+1)*64 + xc];
            asm volatile("cp.async.wait_group 1;");
        } else {
            asm volatile("cp.async.wait_group 0;");
        }
        __syncthreads();                          // chunk c staged

        #pragma unroll
        for (int sub = 0; sub < 4; sub++) {
            uint32_t ah[4];
            int ar = w4*16 + (lane & 15), ac = sub*16 + ((lane >> 4) << 3);
            ldsm4(ah, smaddr(xh + ar*144 + ac*2));
            int br = sub*16 + (g & 1)*8 + rl;
            #pragma unroll
            for (int j = 0; j < 6; j++) {
                int bc = wg*96 + j*16 + (g >> 1)*8;
                uint32_t bh[4];
                ldsm4t(bh, smaddr(wsb + br*400 + bc*2));
                mma16816(acc[2*j],   ah, bh);
                mma16816(acc[2*j+1], ah, bh + 2);
            }
        }
    }

    // epilogue (layout per wg: K[32] | Q[32] | V[32], h = wg*32 + (r&31))
    const int rl4 = lane >> 2, q2 = (lane & 3)*2;
    #pragma unroll
    for (int j = 0; j < 6; j++) {
        #pragma unroll
        for (int h2 = 0; h2 < 2; h2++) {
            int r = j*16 + h2*8 + q2;              // 0..95 within wg
            int type = r >> 5;
            int hc = wg*32 + (r & 31);
            #pragma unroll
            for (int er = 0; er < 2; er++) {
                float v0 = acc[2*j+h2][er*2], v1 = acc[2*j+h2][er*2+1];
                size_t roff = (size_t)(row0 + w4*16 + rl4 + er*8)*HH + hc;
                if (type == 0) {
                    *(__half2*)&g_kh[roff] = __floats2half2_rn(v0, v1);
                } else if (type == 2) {
                    *(__half2*)&g_vh[roff] = __floats2half2_rn(v0, v1);
                } else {
                    *(__half2*)&g_qh[roff] =
                        __floats2half2_rn(v0*QSCALE, v1*QSCALE);
                }
            }
        }
    }
}

// ---------------------------------------------------------------------------
// Flash attention, split-KV (SPL=4): CTA (qt, js) does kt = js, js+4, ... <= qt.
// q pre-scaled by 0.125*log2(e); softmax in exp2 domain. Partials fp16.
// smem: Qh [64][72] @0 (9216 B), KV bufs @4608 halfs.
// ---------------------------------------------------------------------------
#define ATT_SMEM_BYTES ((4608 + 2*9216) * 2)      // 46080

__device__ __forceinline__ void kv_prefetch(__half* sh, int buf, size_t gbase,
                                            int tid)
{
    __half* base = sh + 4608 + buf*9216;
    #pragma unroll
    for (int i = 0; i < 8; i++) {
        int j = tid + i*128;
        int surf = j >> 9, rc = j & 511;
        int r = rc >> 3, c = (rc & 7)*8;
        CPA16(smaddr(base + surf*4608 + r*72 + c),
              (surf ? g_vh : g_kh) + gbase + r*64 + c);
    }
}

__global__ __launch_bounds__(128) void attn_kernel()
{
    extern __shared__ __half sh[];
    __half* Qh = sh;

    const int tid = threadIdx.x;
    const int w = tid >> 5, lane = tid & 31;
    const int qt = NQT - 1 - ((int)blockIdx.x >> 2);
    const int js = blockIdx.x & 3;
    const int b = blockIdx.y;
    const int chunk = (b*NQT + qt)*SPL + js;
    __half* poh = g_pOh + (size_t)chunk*4096;

    if (js > qt) return;                          // merge handles empty splits

    const size_t kvb = (size_t)b*TT*HH;
    kv_prefetch(sh, 0, kvb + (size_t)js*64*HH, tid);
    CPA_COMMIT();

    {
        const size_t qb = kvb + (size_t)qt*64*HH;
        #pragma unroll
        for (int i = 0; i < 4; i++) {
            int idx = tid + i*128; int r = idx >> 3, c = (idx & 7)*8;
            *(int4*)&Qh[r*72 + c] = *(const int4*)&g_qh[qb + r*64 + c];
        }
    }
    __syncthreads();

    uint32_t aq[4][4];
    #pragma unroll
    for (int kc = 0; kc < 4; kc++) {
        int r = w*16 + (lane & 15), c = kc*16 + ((lane >> 4) << 3);
        ldsm4(aq[kc], smaddr(&Qh[r*72 + c]));
    }

    float o[8][4];
    #pragma unroll
    for (int nt = 0; nt < 8; nt++)
        #pragma unroll
        for (int e = 0; e < 4; e++) o[nt][e] = 0.f;
    float m0 = -1e9f, m1 = -1e9f, l0 = 0.f, l1 = 0.f;

    #pragma unroll 1
    for (int kt = js; kt <= qt; kt += SPL) {
        __syncthreads();
        if (kt + SPL <= qt) {
            kv_prefetch(sh, ((kt - js) >> 2 & 1) ^ 1,
                        kvb + (size_t)(kt + SPL)*64*HH, tid);
            CPA_COMMIT();
            asm volatile("cp.async.wait_group 1;");
        } else {
            asm volatile("cp.async.wait_group 0;");
        }
        __syncthreads();

        __half* Khp = sh + 4608 + ((kt - js) >> 2 & 1)*9216;
        __half* Vsp = Khp + 4608;

        float s[8][4];
        #pragma unroll
        for (int nt = 0; nt < 8; nt++)
            #pragma unroll
            for (int e = 0; e < 4; e++) s[nt][e] = 0.f;
        const int g = lane >> 3, rl8 = lane & 7;
        #pragma unroll
        for (int kc = 0; kc < 4; kc++) {
            #pragma unroll
            for (int jj = 0; jj < 4; jj++) {
                int r = jj*16 + (g >> 1)*8 + rl8;
                int ccol = kc*16 + (g & 1)*8;
                uint32_t bh[4];
                ldsm4(bh, smaddr(&Khp[r*72 + ccol]));
                mma16816(s[2*jj],   aq[kc], bh);
                mma16816(s[2*jj+1], aq[kc], bh + 2);
            }
        }

        if (kt == qt) {
            int r0l = w*16 + (lane >> 2);
            int c0l = (lane & 3)*2;
            #pragma unroll
            for (int nt = 0; nt < 8; nt++) {
                int c = nt*8 + c0l;
                if (c     > r0l)     s[nt][0] = -1e9f;
                if (c + 1 > r0l)     s[nt][1] = -1e9f;
                if (c     > r0l + 8) s[nt][2] = -1e9f;
                if (c + 1 > r0l + 8) s[nt][3] = -1e9f;
            }
        }

        float rm0 = -1e9f, rm1 = -1e9f;
        #pragma unroll
        for (int nt = 0; nt < 8; nt++) {
            rm0 = fmaxf(rm0, fmaxf(s[nt][0], s[nt][1]));
            rm1 = fmaxf(rm1, fmaxf(s[nt][2], s[nt][3]));
        }
        rm0 = fmaxf(rm0, __shfl_xor_sync(0xffffffffu, rm0, 1));
        rm0 = fmaxf(rm0, __shfl_xor_sync(0xffffffffu, rm0, 2));
        rm1 = fmaxf(rm1, __shfl_xor_sync(0xffffffffu, rm1, 1));
        rm1 = fmaxf(rm1, __shfl_xor_sync(0xffffffffu, rm1, 2));
        float mn0 = fmaxf(m0, rm0), mn1 = fmaxf(m1, rm1);
        float corr0 = ex2(m0 - mn0), corr1 = ex2(m1 - mn1);
        m0 = mn0; m1 = mn1;
        float rs0 = 0.f, rs1 = 0.f;
        #pragma unroll
        for (int nt = 0; nt < 8; nt++) {
            s[nt][0] = ex2(s[nt][0] - mn0); rs0 += s[nt][0];
            s[nt][1] = ex2(s[nt][1] - mn0); rs0 += s[nt][1];
            s[nt][2] = ex2(s[nt][2] - mn1); rs1 += s[nt][2];
            s[nt][3] = ex2(s[nt][3] - mn1); rs1 += s[nt][3];
        }
        rs0 += __shfl_xor_sync(0xffffffffu, rs0, 1);
        rs0 += __shfl_xor_sync(0xffffffffu, rs0, 2);
        rs1 += __shfl_xor_sync(0xffffffffu, rs1, 1);
        rs1 += __shfl_xor_sync(0xffffffffu, rs1, 2);
        l0 = l0*corr0 + rs0;
        l1 = l1*corr1 + rs1;
        #pragma unroll
        for (int nt = 0; nt < 8; nt++) {
            o[nt][0] *= corr0; o[nt][1] *= corr0;
            o[nt][2] *= corr1; o[nt][3] *= corr1;
        }

        #pragma unroll
        for (int kc = 0; kc < 4; kc++) {
            uint32_t ap[4];
            ap[0] = packh2(s[2*kc][0],   s[2*kc][1]);
            ap[1] = packh2(s[2*kc][2],   s[2*kc][3]);
            ap[2] = packh2(s[2*kc+1][0], s[2*kc+1][1]);
            ap[3] = packh2(s[2*kc+1][2], s[2*kc+1][3]);
            #pragma unroll
            for (int jj = 0; jj < 4; jj++) {
                int r = kc*16 + (g & 1)*8 + rl8;
                int ccol = jj*16 + (g >> 1)*8;
                uint32_t vb[4];
                ldsm4t(vb, smaddr(&Vsp[r*72 + ccol]));
                mma16816(o[2*jj],   ap, vb);
                mma16816(o[2*jj+1], ap, vb + 2);
            }
        }
    }

    const int r0 = w*16 + (lane >> 2);
    #pragma unroll
    for (int nt = 0; nt < 8; nt++) {
        int c = nt*8 + (lane & 3)*2;
        *(uint32_t*)&poh[r0*64 + c]     = packh2(o[nt][0], o[nt][1]);
        *(uint32_t*)&poh[(r0+8)*64 + c] = packh2(o[nt][2], o[nt][3]);
    }
    if ((lane & 3) == 0) {
        g_pML[chunk*64 + r0]     = make_float2(m0, l0);
        g_pML[chunk*64 + r0 + 8] = make_float2(m1, l1);
    }
}

// ---------------------------------------------------------------------------
// Merge: fp16 partials, exp2 domain; splits j > qt are empty (weight 0).
// 512 threads; thread = (row, 8-col group).
// ---------------------------------------------------------------------------
__global__ __launch_bounds__(512) void merge_kernel(float* __restrict__ out)
{
    const int qt = blockIdx.x, b = blockIdx.y;
    const int tid = threadIdx.x;
    const int r = tid >> 3;                       // 0..63
    const int c8 = (tid & 7)*8;
    const int c0 = (b*NQT + qt)*SPL;

    float2 ml[SPL];
    uint4 ph[SPL];
    #pragma unroll
    for (int j = 0; j < SPL; j++) {
        if (j <= qt) {
            ml[j] = g_pML[(c0 + j)*64 + r];
            ph[j] = *(const uint4*)&g_pOh[(size_t)(c0 + j)*4096 + r*64 + c8];
        } else {
            ml[j] = make_float2(-1e30f, 0.f);
            ph[j] = make_uint4(0u, 0u, 0u, 0u);
        }
    }
    float M = -1e30f;
    #pragma unroll
    for (int j = 0; j < SPL; j++) M = fmaxf(M, ml[j].x);
    float wsum = 0.f, wj[SPL];
    #pragma unroll
    for (int j = 0; j < SPL; j++) {
        wj[j] = ex2(ml[j].x - M);
        wsum += wj[j]*ml[j].y;
    }
    const float inv = 1.0f/wsum;

    float a[8];
    #pragma unroll
    for (int i = 0; i < 8; i++) a[i] = 0.f;
    #pragma unroll
    for (int j = 0; j < SPL; j++) {
        const uint32_t* u = (const uint32_t*)&ph[j];
        #pragma unroll
        for (int p = 0; p < 4; p++) {
            float2 v = __half22float2(*(const __half2*)&u[p]);
            a[2*p]   += wj[j]*v.x;
            a[2*p+1] += wj[j]*v.y;
        }
    }
    size_t off = ((size_t)b*TT + qt*64 + r)*HH + c8;
    *(float4*)&out[off]     = make_float4(a[0]*inv, a[1]*inv, a[2]*inv, a[3]*inv);
    *(float4*)&out[off + 4] = make_float4(a[4]*inv, a[5]*inv, a[6]*inv, a[7]*inv);
}

extern "C" void kernel_launch(void* const* d_in, const int* in_sizes, int n_in,
                              void* d_out, int out_size) {
    const float* x  = (const float*)d_in[0];
    const float* Wk = (const float*)d_in[1];
    const float* Wq = (const float*)d_in[2];
    const float* Wv = (const float*)d_in[3];
    float* out = (float*)d_out;

    static int init = 0;
    if (!init) {
        cudaFuncSetAttribute(proj_kernel,
            cudaFuncAttributeMaxDynamicSharedMemorySize, PROJ_SMEM);
        cudaFuncSetAttribute(attn_kernel,
            cudaFuncAttributeMaxDynamicSharedMemorySize, ATT_SMEM_BYTES);
        init = 1;
    }

    wprep_kernel<<<768, 256>>>(Wk, Wq, Wv);
    proj_kernel<<<(BB*TT)/64, 256, PROJ_SMEM>>>(x);
    attn_kernel<<<dim3(NQT*SPL, BB), 128, ATT_SMEM_BYTES>>>();
    merge_kernel<<<dim3(NQT, BB), 512>>>(out);
}